// round 16
// baseline (speedup 1.0000x reference)
#include <cuda_runtime.h>
#include <cuda_bf16.h>
#include <math.h>

// ---------------- problem constants ----------------
#define BSZ 4
#define NV  2048

// ---------------- device scratch ----------------
__device__ float g_d0[3*896];
__device__ float g_d1[3*896];
__device__ float g_d2[3*1792];
__device__ float g_d3[3*1792];
__device__ float g_d4[3*3584];

__device__ float4 g_pts4[BSZ*NV];

__device__ int   g_nb  [BSZ*NV*10];
__device__ int   g_nb1 [BSZ*512*10];
__device__ int   g_nb2 [BSZ*128*10];
__device__ int   g_nbp1[BSZ*512*4];
__device__ int   g_nbp2[BSZ*128*4];
__device__ int   g_n1  [BSZ*NV];
__device__ int   g_n2  [BSZ*NV];

__device__ float g_fm0[BSZ*NV*128];
__device__ float g_fo1[BSZ*NV*1024];
__device__ float g_cv1[BSZ*NV*128];
__device__ float g_fm1[BSZ*NV*128];
__device__ float g_fp1[BSZ*512*128];
__device__ float g_fo2[BSZ*512*2048];
__device__ float g_cv2[BSZ*512*256];
__device__ float g_fm2[BSZ*512*256];
__device__ float g_fo3[BSZ*512*2048];
__device__ float g_cv3[BSZ*512*256];
__device__ float g_fm3[BSZ*512*256];
__device__ float g_fp2[BSZ*128*256];
__device__ float g_fo4[BSZ*128*4096];
__device__ float g_fm4[BSZ*128*512];
__device__ float g_fg [BSZ*512];
__device__ float g_f01[BSZ*NV*256];
__device__ float g_f23[BSZ*512*512];
__device__ float g_pA [BSZ*NV*512];
__device__ float g_pB [BSZ*512*512];
__device__ float g_pC [BSZ*128*512];
__device__ float g_pDE[BSZ*512];
__device__ float g_h1 [BSZ*NV*512];
__device__ float g_h2 [BSZ*NV*512];
// BN accumulators: [s1 128 | q1 128 | s2 256 | q2 256 | s3 256 | q3 256]
__device__ float g_bnacc[1280];

// ---------------- kNN (dot-product form, packed float4 points) ----------------
template <int KN, int SUB>
__global__ void k_knn(const float4* __restrict__ pts4, int bstride, int N, int Q,
                      int* __restrict__ out) {
    extern __shared__ float4 sp4[];
    float* smd = (float*)(sp4 + N);
    int* smi = (int*)(smd + 256 * KN);
    const int QPB = 256 / SUB;
    int b = blockIdx.y;
    const float4* P = pts4 + (size_t)b * bstride;
    for (int i = threadIdx.x; i < N; i += blockDim.x) sp4[i] = P[i];
    __syncthreads();
    int sub = threadIdx.x % SUB;
    int ql = threadIdx.x / SUB;
    int q = blockIdx.x * QPB + ql;
    float bd[KN]; int bi[KN];
#pragma unroll
    for (int i = 0; i < KN; i++) { bd[i] = 3.4e38f; bi[i] = 0x7fffffff; }
    if (q < Q) {
        float4 qp = sp4[q];
        float nqx = -2.f * qp.x, nqy = -2.f * qp.y, nqz = -2.f * qp.z;
#pragma unroll 4
        for (int j = sub; j < N; j += SUB) {
            float4 p = sp4[j];
            float d = fmaf(p.x, nqx, fmaf(p.y, nqy, fmaf(p.z, nqz, p.w)));
            if (d < bd[KN - 1] && j != q) {
                bd[KN - 1] = d; bi[KN - 1] = j;
#pragma unroll
                for (int r = KN - 1; r > 0; --r) {
                    if (bd[r] < bd[r - 1]) {
                        float td = bd[r]; bd[r] = bd[r - 1]; bd[r - 1] = td;
                        int ti = bi[r]; bi[r] = bi[r - 1]; bi[r - 1] = ti;
                    }
                }
            }
        }
    }
    int base = threadIdx.x * KN;
#pragma unroll
    for (int i = 0; i < KN; i++) { smd[base + i] = bd[i]; smi[base + i] = bi[i]; }
    if (SUB > 4) __syncthreads(); else __syncwarp();
    if (sub == 0 && q < Q) {
        int p[SUB];
#pragma unroll
        for (int l = 0; l < SUB; l++) p[l] = 0;
        int lbase = ql * SUB * KN;
        int* o = out + ((size_t)b * Q + q) * KN;
#pragma unroll
        for (int k = 0; k < KN; k++) {
            float best = 3.5e38f; int bidx = 0x7fffffff; int bl = 0;
#pragma unroll
            for (int l = 0; l < SUB; l++) {
                int pp = p[l];
                float d = (pp < KN) ? smd[lbase + l * KN + pp] : 3.6e38f;
                int ix = (pp < KN) ? smi[lbase + l * KN + pp] : 0x7fffffff;
                if (d < best || (d == best && ix < bidx)) { best = d; bidx = ix; bl = l; }
            }
            p[bl]++;
            o[k] = bidx;
        }
    }
}

__global__ void k_nearest(const float4* __restrict__ pts4, int bstride, int Nt, int Ns,
                          int* __restrict__ out) {
    extern __shared__ float4 sp4[];
    int b = blockIdx.y;
    const float4* P = pts4 + (size_t)b * bstride;
    for (int i = threadIdx.x; i < Ns; i += blockDim.x) sp4[i] = P[i];
    __syncthreads();
    int t = blockIdx.x * blockDim.x + threadIdx.x;
    if (t >= Nt) return;
    float4 qp = pts4[(size_t)b * bstride + t];
    float nqx = -2.f * qp.x, nqy = -2.f * qp.y, nqz = -2.f * qp.z;
    float best = 3.4e38f; int bi = 0;
#pragma unroll 4
    for (int j = 0; j < Ns; j++) {
        float4 p = sp4[j];
        float d = fmaf(p.x, nqx, fmaf(p.y, nqy, fmaf(p.z, nqz, p.w)));
        if (d < best) { best = d; bi = j; }
    }
    out[(size_t)b * Nt + t] = bi;
}

// ---------------- streams/events ----------------
static cudaStream_t s_a = 0, s_b = 0;
static cudaEvent_t ev_fork, ev_nm, ev_ja, ev_jn1, ev_jb, ev_bn1, ev_pa, ev_bn3, ev_pc, ev_l4, ev_asm;

struct _StreamInit {
    _StreamInit() {
        cudaStreamCreateWithFlags(&s_a, cudaStreamNonBlocking);
        cudaStreamCreateWithFlags(&s_b, cudaStreamNonBlocking);
        cudaEventCreateWithFlags(&ev_fork, cudaEventDisableTiming);
        cudaEventCreateWithFlags(&ev_nm, cudaEventDisableTiming);
        cudaEventCreateWithFlags(&ev_ja, cudaEventDisableTiming);
        cudaEventCreateWithFlags(&ev_jn1, cudaEventDisableTiming);
        cudaEventCreateWithFlags(&ev_jb, cudaEventDisableTiming);
        cudaEventCreateWithFlags(&ev_bn1, cudaEventDisableTiming);
        cudaEventCreateWithFlags(&ev_pa, cudaEventDisableTiming);
        cudaEventCreateWithFlags(&ev_bn3, cudaEventDisableTiming);
        cudaEventCreateWithFlags(&ev_pc, cudaEventDisableTiming);
        cudaEventCreateWithFlags(&ev_l4, cudaEventDisableTiming);
        cudaEventCreateWithFlags(&ev_asm, cudaEventDisableTiming);
        cudaFuncSetAttribute(k_knn<10, 16>, cudaFuncAttributeMaxDynamicSharedMemorySize,
                             NV * 16 + 256 * 10 * 8);
        cudaFuncSetAttribute(k_knn<4, 16>, cudaFuncAttributeMaxDynamicSharedMemorySize,
                             NV * 16 + 256 * 4 * 8);
        cudaFuncSetAttribute(k_knn<10, 8>, cudaFuncAttributeMaxDynamicSharedMemorySize,
                             NV * 16 + 256 * 10 * 8);
        cudaFuncSetAttribute(k_knn<4, 8>, cudaFuncAttributeMaxDynamicSharedMemorySize,
                             NV * 16 + 256 * 4 * 8);
    }
};
static _StreamInit g_stream_init;

// ---------------- misc kernels ----------------

__global__ void k_prep_pts(const float* __restrict__ verts, float4* __restrict__ pts4,
                           float* __restrict__ bnacc) {
    int i = blockIdx.x * blockDim.x + threadIdx.x;
    if (i < 1280) bnacc[i] = 0.f;
    if (i >= BSZ * NV) return;
    float x = verts[i * 3], y = verts[i * 3 + 1], z = verts[i * 3 + 2];
    pts4[i] = make_float4(x, y, z, x * x + y * y + z * z);
}

__global__ void k_norm_all(const float* __restrict__ d0, const float* __restrict__ d1,
                           const float* __restrict__ d2, const float* __restrict__ d3,
                           const float* __restrict__ d4,
                           float* __restrict__ o0, float* __restrict__ o1,
                           float* __restrict__ o2, float* __restrict__ o3,
                           float* __restrict__ o4) {
    int i = blockIdx.x * blockDim.x + threadIdx.x;
    const float* src; float* dst; int D, c;
    if (i < 896)        { src = d0; dst = o0; D = 896;  c = i; }
    else if (i < 1792)  { src = d1; dst = o1; D = 896;  c = i - 896; }
    else if (i < 3584)  { src = d2; dst = o2; D = 1792; c = i - 1792; }
    else if (i < 5376)  { src = d3; dst = o3; D = 1792; c = i - 3584; }
    else if (i < 8960)  { src = d4; dst = o4; D = 3584; c = i - 5376; }
    else return;
    float x = src[c], y = src[D + c], z = src[2 * D + c];
    float inv = 1.f / fmaxf(sqrtf(x * x + y * y + z * z), 1e-12f);
    dst[c] = x * inv; dst[D + c] = y * inv; dst[2 * D + c] = z * inv;
}

__global__ void k_conv_surface(const float* __restrict__ verts, const int* __restrict__ nb,
                               const float* __restrict__ sd, float* __restrict__ out,
                               float* __restrict__ f01) {
    int b = blockIdx.y, v = blockIdx.x;
    __shared__ float nd[10][3];
    size_t row = (size_t)b * NV + v;
    if (threadIdx.x < 10) {
        int j = nb[row * 10 + threadIdx.x];
        const float* c0 = verts + row * 3;
        const float* c1 = verts + ((size_t)b * NV + j) * 3;
        float dx = c1[0] - c0[0], dy = c1[1] - c0[1], dz = c1[2] - c0[2];
        float inv = 1.f / fmaxf(sqrtf(dx * dx + dy * dy + dz * dz), 1e-12f);
        nd[threadIdx.x][0] = dx * inv; nd[threadIdx.x][1] = dy * inv; nd[threadIdx.x][2] = dz * inv;
    }
    __syncthreads();
    int c = threadIdx.x;
    float acc = 0.f;
#pragma unroll
    for (int s = 0; s < 7; s++) {
        int col = s * 128 + c;
        float sx = sd[col], sy = sd[896 + col], sz = sd[1792 + col];
        float m = 0.f;
#pragma unroll
        for (int n = 0; n < 10; n++) {
            float t = nd[n][0] * sx + nd[n][1] * sy + nd[n][2] * sz;
            m = fmaxf(m, t);
        }
        acc += m;
    }
    float r = fmaxf(acc, 0.f);
    out[row * 128 + c] = r;
    f01[row * 256 + c] = r;
}

__global__ void k_conv_layer(const float* __restrict__ verts, int vstride, int V,
                             const int* __restrict__ nb, const float* __restrict__ fo,
                             const float* __restrict__ sd, int OC, float* __restrict__ out) {
    int b = blockIdx.y, v = blockIdx.x;
    __shared__ float nd[10][3];
    __shared__ int nidx[10];
    if (threadIdx.x < 10) {
        int j = nb[((size_t)b * V + v) * 10 + threadIdx.x];
        nidx[threadIdx.x] = j;
        const float* c0 = verts + ((size_t)b * vstride + v) * 3;
        const float* c1 = verts + ((size_t)b * vstride + j) * 3;
        float dx = c1[0] - c0[0], dy = c1[1] - c0[1], dz = c1[2] - c0[2];
        float inv = 1.f / fmaxf(sqrtf(dx * dx + dy * dy + dz * dz), 1e-12f);
        nd[threadIdx.x][0] = dx * inv; nd[threadIdx.x][1] = dy * inv; nd[threadIdx.x][2] = dz * inv;
    }
    __syncthreads();
    int c = threadIdx.x;
    int FW = 8 * OC, D = 7 * OC;
    const float* base = fo + (size_t)b * V * FW;
    float acc = base[(size_t)v * FW + c];
#pragma unroll
    for (int s = 0; s < 7; s++) {
        int col = s * OC + c;
        float sx = sd[col], sy = sd[D + col], sz = sd[2 * D + col];
        float m = -3.4e38f;
#pragma unroll
        for (int n = 0; n < 10; n++) {
            float t = fmaxf(nd[n][0] * sx + nd[n][1] * sy + nd[n][2] * sz, 0.f);
            float sup = base[(size_t)nidx[n] * FW + OC + col];
            m = fmaxf(m, t * sup);
        }
        acc += m;
    }
    out[((size_t)b * V + v) * OC + c] = acc;
}

__global__ void k_bn_stats_at(const float* __restrict__ x, int R, int C,
                              float* __restrict__ sum, float* __restrict__ sq) {
    int c = blockIdx.x * 32 + threadIdx.x;
    int rows = R / gridDim.y;
    int r0 = blockIdx.y * rows;
    float s = 0.f, s2 = 0.f;
    for (int r = r0 + threadIdx.y; r < r0 + rows; r += 32) {
        float v = x[(size_t)r * C + c];
        s += v; s2 += v * v;
    }
    __shared__ float sh[32][33], sh2[32][33];
    sh[threadIdx.y][threadIdx.x] = s; sh2[threadIdx.y][threadIdx.x] = s2;
    __syncthreads();
    if (threadIdx.y == 0) {
        float ts = 0.f, ts2 = 0.f;
#pragma unroll
        for (int y = 0; y < 32; y++) { ts += sh[y][threadIdx.x]; ts2 += sh2[y][threadIdx.x]; }
        atomicAdd(&sum[c], ts);
        atomicAdd(&sq[c], ts2);
    }
}

__global__ void k_bn_apply(const float* __restrict__ x, const float* __restrict__ sum,
                           const float* __restrict__ sq, const float* __restrict__ g,
                           const float* __restrict__ be, float* __restrict__ y,
                           int total, int C, int Cy, int coff, float Rinv,
                           float* __restrict__ y2) {
    int i = blockIdx.x * blockDim.x + threadIdx.x;
    if (i >= total) return;
    int c = i % C;
    int r = i / C;
    float m = sum[c] * Rinv;
    float var = sq[c] * Rinv - m * m;
    float v = (x[i] - m) * rsqrtf(var + 1e-5f) * g[c] + be[c];
    v = fmaxf(v, 0.f);
    y[(size_t)r * Cy + coff + c] = v;
    if (y2) y2[i] = v;
}

__global__ void k_pool(const float* __restrict__ fm, int Vin, const int* __restrict__ nbp,
                       int C, float* __restrict__ out) {
    int b = blockIdx.y, p = blockIdx.x, c = threadIdx.x;
    int P = gridDim.x;
    const int* nr = nbp + ((size_t)b * P + p) * 4;
    float m = -3.4e38f;
#pragma unroll
    for (int j = 0; j < 4; j++)
        m = fmaxf(m, fm[((size_t)b * Vin + nr[j]) * C + c]);
    out[((size_t)b * P + p) * C + c] = m;
}

__global__ void k_fglobal(const float* __restrict__ fm4, float* __restrict__ fg) {
    int b = blockIdx.x, c = threadIdx.x;
    float m = -3.4e38f;
    for (int r = 0; r < 128; r++)
        m = fmaxf(m, fm4[((size_t)b * 128 + r) * 512 + c]);
    fg[b * 512 + c] = m;
}

__global__ void k_assemble(const float* __restrict__ fm0, const float* __restrict__ fm1,
                           const float* __restrict__ fm2, const float* __restrict__ fm3,
                           const float* __restrict__ fm4, const float* __restrict__ onehot,
                           const int* __restrict__ n1, const int* __restrict__ n2,
                           float* __restrict__ feat) {
    int b = blockIdx.y, v = blockIdx.x;
    size_t row = (size_t)b * NV + v;
    int i1 = n1[row], i2 = n2[row];
    float* fe = feat + row * 1296;
    for (int c = threadIdx.x; c < 1296; c += blockDim.x) {
        float val;
        if (c < 128)        val = fm0[row * 128 + c];
        else if (c < 256)   val = fm1[row * 128 + (c - 128)];
        else if (c < 512)   val = fm2[((size_t)b * 512 + i1) * 256 + (c - 256)];
        else if (c < 768)   val = fm3[((size_t)b * 512 + i1) * 256 + (c - 512)];
        else if (c < 1280)  val = fm4[((size_t)b * 128 + i2) * 512 + (c - 768)];
        else                val = onehot[b * 16 + (c - 1280)];
        fe[c] = val;
    }
}

__global__ void k_pde(const float* __restrict__ fg, const float* __restrict__ onehot,
                      const float* __restrict__ wc1, const float* __restrict__ bc1,
                      float* __restrict__ pde) {
    int b = blockIdx.y;
    int o = blockIdx.x * 8 + (threadIdx.x >> 5);
    int lane = threadIdx.x & 31;
    const float* w = wc1 + (size_t)o * 1808;
    float s = 0.f;
    for (int c = lane; c < 512; c += 32) s = fmaf(fg[b * 512 + c], w[1280 + c], s);
    if (lane < 16) s = fmaf(onehot[b * 16 + lane], w[1792 + lane], s);
#pragma unroll
    for (int off = 16; off; off >>= 1) s += __shfl_down_sync(0xffffffffu, s, off);
    if (lane == 0) pde[b * 512 + o] = s + bc1[o];
}

__global__ void k_combine(const float* __restrict__ pA, const float* __restrict__ pB,
                          const float* __restrict__ pC, const float* __restrict__ pDE,
                          const int* __restrict__ n1, const int* __restrict__ n2,
                          float* __restrict__ h1) {
    int row = blockIdx.x;
    int b = row >> 11;
    int i1 = n1[row], i2 = n2[row];
    const float4* a  = (const float4*)(pA + (size_t)row * 512);
    const float4* pb = (const float4*)(pB + ((size_t)b * 512 + i1) * 512);
    const float4* pc = (const float4*)(pC + ((size_t)b * 128 + i2) * 512);
    const float4* pd = (const float4*)(pDE + (size_t)b * 512);
    float4* o = (float4*)(h1 + (size_t)row * 512);
    for (int c = threadIdx.x; c < 128; c += blockDim.x) {
        float4 va = a[c], vb = pb[c], vc = pc[c], vd = pd[c];
        float4 r;
        r.x = fmaxf(va.x + vb.x + vc.x + vd.x, 0.f);
        r.y = fmaxf(va.y + vb.y + vc.y + vd.y, 0.f);
        r.z = fmaxf(va.z + vb.z + vc.z + vd.z, 0.f);
        r.w = fmaxf(va.w + vb.w + vc.w + vd.w, 0.f);
        o[c] = r;
    }
}

// ---------------- 3xBF16 tensor-core GEMM ----------------
__device__ __forceinline__ void split_bf16_pair(float x0, float x1,
                                                unsigned& hi, unsigned& lo) {
    __nv_bfloat162 h = __floats2bfloat162_rn(x0, x1);
    float r0 = x0 - __bfloat162float(h.x);
    float r1 = x1 - __bfloat162float(h.y);
    __nv_bfloat162 l = __floats2bfloat162_rn(r0, r1);
    hi = *reinterpret_cast<unsigned*>(&h);
    lo = *reinterpret_cast<unsigned*>(&l);
}

#define MMA16(acc, a0, a1, a2, a3, b0, b1)                                    \
    asm volatile(                                                             \
        "mma.sync.aligned.m16n8k16.row.col.f32.bf16.bf16.f32 "                \
        "{%0,%1,%2,%3}, {%4,%5,%6,%7}, {%8,%9}, {%0,%1,%2,%3};\n"             \
        : "+f"(acc[0]), "+f"(acc[1]), "+f"(acc[2]), "+f"(acc[3])              \
        : "r"(a0), "r"(a1), "r"(a2), "r"(a3), "r"(b0), "r"(b1))

template <bool BT, bool RELU, bool BIAS>
__global__ void __launch_bounds__(256)
k_gemm_bf16x3(const float* __restrict__ A, const float* __restrict__ B,
              const float* __restrict__ bias, float* __restrict__ C,
              int M, int N, int K, int ldb) {
    __shared__ unsigned Ah[8][136], Al[8][136];
    __shared__ unsigned Bh[8][136], Bl[8][136];
    int tid = threadIdx.x;
    int lane = tid & 31, warp = tid >> 5;
    int wm = (warp & 1) * 64, wn = (warp >> 1) * 32;
    int bm = blockIdx.y * 128, bn = blockIdx.x * 128;

    float acc[4][4][4];
#pragma unroll
    for (int i = 0; i < 4; i++)
#pragma unroll
        for (int j = 0; j < 4; j++)
#pragma unroll
            for (int k = 0; k < 4; k++) acc[i][j][k] = 0.f;

    float4 pa[2];
    float4 pbt[2];
    float2 pbn0[2], pbn1[2];

#define LOAD_AB(k0)                                                             \
    _Pragma("unroll")                                                           \
    for (int i = 0; i < 2; i++) {                                               \
        int idx = tid + i * 256;                                                \
        pa[i] = *reinterpret_cast<const float4*>(                               \
            A + (size_t)(bm + (idx & 127)) * K + (k0) + (idx >> 7) * 4);        \
        if (BT) {                                                               \
            pbt[i] = *reinterpret_cast<const float4*>(                          \
                B + (size_t)(bn + (idx & 127)) * ldb + (k0) + (idx >> 7) * 4);  \
        } else {                                                                \
            int pr = idx >> 6, n2 = (idx & 63) * 2;                             \
            pbn0[i] = *reinterpret_cast<const float2*>(                         \
                B + (size_t)((k0) + 2 * pr) * ldb + bn + n2);                   \
            pbn1[i] = *reinterpret_cast<const float2*>(                         \
                B + (size_t)((k0) + 2 * pr + 1) * ldb + bn + n2);               \
        }                                                                       \
    }
#define STORE_AB()                                                              \
    _Pragma("unroll")                                                           \
    for (int i = 0; i < 2; i++) {                                               \
        int idx = tid + i * 256;                                                \
        int ar = idx & 127, apr = (idx >> 7) * 2;                               \
        split_bf16_pair(pa[i].x, pa[i].y, Ah[apr][ar], Al[apr][ar]);            \
        split_bf16_pair(pa[i].z, pa[i].w, Ah[apr + 1][ar], Al[apr + 1][ar]);    \
        if (BT) {                                                               \
            split_bf16_pair(pbt[i].x, pbt[i].y, Bh[apr][ar], Bl[apr][ar]);      \
            split_bf16_pair(pbt[i].z, pbt[i].w, Bh[apr + 1][ar], Bl[apr + 1][ar]); \
        } else {                                                                \
            int pr = idx >> 6, n2 = (idx & 63) * 2;                             \
            split_bf16_pair(pbn0[i].x, pbn1[i].x, Bh[pr][n2], Bl[pr][n2]);      \
            split_bf16_pair(pbn0[i].y, pbn1[i].y, Bh[pr][n2 + 1], Bl[pr][n2 + 1]); \
        }                                                                       \
    }

    LOAD_AB(0);
    STORE_AB();
    __syncthreads();

    int r = lane >> 2, cq = lane & 3;
    int nT = K / 16;
    for (int t = 0; t < nT; t++) {
        if (t + 1 < nT) {
            int k0 = (t + 1) * 16;
            LOAD_AB(k0);
        }
        unsigned afh[4][4], afl[4][4], bfh[4][2], bfl[4][2];
#pragma unroll
        for (int mf = 0; mf < 4; mf++) {
            int m0 = wm + mf * 16 + r;
            afh[mf][0] = Ah[cq][m0];         afl[mf][0] = Al[cq][m0];
            afh[mf][1] = Ah[cq][m0 + 8];     afl[mf][1] = Al[cq][m0 + 8];
            afh[mf][2] = Ah[cq + 4][m0];     afl[mf][2] = Al[cq + 4][m0];
            afh[mf][3] = Ah[cq + 4][m0 + 8]; afl[mf][3] = Al[cq + 4][m0 + 8];
        }
#pragma unroll
        for (int nf = 0; nf < 4; nf++) {
            int n0 = wn + nf * 8 + r;
            bfh[nf][0] = Bh[cq][n0];     bfl[nf][0] = Bl[cq][n0];
            bfh[nf][1] = Bh[cq + 4][n0]; bfl[nf][1] = Bl[cq + 4][n0];
        }
#pragma unroll
        for (int mf = 0; mf < 4; mf++)
#pragma unroll
            for (int nf = 0; nf < 4; nf++) {
                MMA16(acc[mf][nf], afh[mf][0], afh[mf][1], afh[mf][2], afh[mf][3],
                      bfl[nf][0], bfl[nf][1]);
                MMA16(acc[mf][nf], afl[mf][0], afl[mf][1], afl[mf][2], afl[mf][3],
                      bfh[nf][0], bfh[nf][1]);
                MMA16(acc[mf][nf], afh[mf][0], afh[mf][1], afh[mf][2], afh[mf][3],
                      bfh[nf][0], bfh[nf][1]);
            }
        if (t + 1 < nT) {
            __syncthreads();
            STORE_AB();
            __syncthreads();
        }
    }

    int c2 = (lane & 3) * 2;
#pragma unroll
    for (int nf = 0; nf < 4; nf++) {
        int col = bn + wn + nf * 8 + c2;
        float b0 = BIAS ? bias[col] : 0.f;
        float b1 = BIAS ? bias[col + 1] : 0.f;
#pragma unroll
        for (int mf = 0; mf < 4; mf++) {
            int row0 = bm + wm + mf * 16 + r;
            float v0 = acc[mf][nf][0] + b0, v1 = acc[mf][nf][1] + b1;
            float v2 = acc[mf][nf][2] + b0, v3 = acc[mf][nf][3] + b1;
            if (RELU) {
                v0 = fmaxf(v0, 0.f); v1 = fmaxf(v1, 0.f);
                v2 = fmaxf(v2, 0.f); v3 = fmaxf(v3, 0.f);
            }
            *reinterpret_cast<float2*>(&C[(size_t)row0 * N + col]) = make_float2(v0, v1);
            *reinterpret_cast<float2*>(&C[(size_t)(row0 + 8) * N + col]) = make_float2(v2, v3);
        }
    }
#undef LOAD_AB
#undef STORE_AB
}

// head GEMM (N=30) fused with seg/vecs split into d_out
#define BM 64
#define BN 64
#define BKK 16
__global__ void k_gemm_head(const float* __restrict__ A, const float* __restrict__ B,
                            const float* __restrict__ bias, float* __restrict__ out,
                            int M, int K) {
    const int N = 30;
    __shared__ __align__(16) float As[BKK][BM + 4];
    __shared__ __align__(16) float Bs[BKK][BN + 4];
    int bm = blockIdx.y * BM;
    int tid = threadIdx.x;
    int tx = tid & 15, ty = tid >> 4;
    float acc[4][4] = {};
    for (int k0 = 0; k0 < K; k0 += BKK) {
#pragma unroll
        for (int i = 0; i < 4; i++) {
            int idx = tid + i * 256;
            int r = idx >> 4, kk = idx & 15;
            As[kk][r] = A[(size_t)(bm + r) * K + k0 + kk];
        }
#pragma unroll
        for (int i = 0; i < 4; i++) {
            int idx = tid + i * 256;
            int n = idx >> 4, kk = idx & 15;
            Bs[kk][n] = (n < N) ? B[(size_t)n * K + k0 + kk] : 0.f;
        }
        __syncthreads();
#pragma unroll
        for (int kk = 0; kk < BKK; kk++) {
            float4 av = *reinterpret_cast<const float4*>(&As[kk][ty * 4]);
            float4 bv = *reinterpret_cast<const float4*>(&Bs[kk][tx * 4]);
            float a[4] = {av.x, av.y, av.z, av.w};
            float bb[4] = {bv.x, bv.y, bv.z, bv.w};
#pragma unroll
            for (int i = 0; i < 4; i++)
#pragma unroll
                for (int j = 0; j < 4; j++)
                    acc[i][j] += a[i] * bb[j];
        }
        __syncthreads();
    }
    size_t voff = (size_t)BSZ * NV * 6;
#pragma unroll
    for (int i = 0; i < 4; i++) {
        int gr = bm + ty * 4 + i;
#pragma unroll
        for (int j = 0; j < 4; j++) {
            int gn = tx * 4 + j;
            if (gn >= N) continue;
            float v = acc[i][j] + bias[gn];
            if (gn < 6)
                out[(size_t)gr * 6 + gn] = v;
            else
                out[voff + (size_t)gr * 24 + (gn - 6)] = v;
        }
    }
}

// ---------------- host ----------------
static inline int cdiv(int a, int b) { return (a + b - 1) / b; }

#define SYMF(p, s) do { void* _t; cudaGetSymbolAddress(&_t, s); p = (float*)_t; } while (0)
#define SYMI(p, s) do { void* _t; cudaGetSymbolAddress(&_t, s); p = (int*)_t; } while (0)

extern "C" void kernel_launch(void* const* d_in, const int* in_sizes, int n_in,
                              void* d_out, int out_size) {
    const float* vertices = (const float*)d_in[0];
    const float* onehot   = (const float*)d_in[1];
    const float* dir0 = (const float*)d_in[2];
    const float* w1   = (const float*)d_in[3];
    const float* b1   = (const float*)d_in[4];
    const float* dir1 = (const float*)d_in[5];
    const float* w2   = (const float*)d_in[6];
    const float* b2   = (const float*)d_in[7];
    const float* dir2 = (const float*)d_in[8];
    const float* w3   = (const float*)d_in[9];
    const float* b3   = (const float*)d_in[10];
    const float* dir3 = (const float*)d_in[11];
    const float* w4   = (const float*)d_in[12];
    const float* b4   = (const float*)d_in[13];
    const float* dir4 = (const float*)d_in[14];
    const float* g_bn1 = (const float*)d_in[15];
    const float* be_bn1 = (const float*)d_in[16];
    const float* g_bn2 = (const float*)d_in[17];
    const float* be_bn2 = (const float*)d_in[18];
    const float* g_bn3 = (const float*)d_in[19];
    const float* be_bn3 = (const float*)d_in[20];
    const float* wc1 = (const float*)d_in[21];
    const float* bc1 = (const float*)d_in[22];
    const float* wc2 = (const float*)d_in[23];
    const float* bc2 = (const float*)d_in[24];
    const float* wc3 = (const float*)d_in[25];
    const float* bc3 = (const float*)d_in[26];
    float* out = (float*)d_out;

    float *p_d0, *p_d1, *p_d2, *p_d3, *p_d4;
    SYMF(p_d0, g_d0); SYMF(p_d1, g_d1); SYMF(p_d2, g_d2); SYMF(p_d3, g_d3); SYMF(p_d4, g_d4);
    float4* p_pts4; { void* _t; cudaGetSymbolAddress(&_t, g_pts4); p_pts4 = (float4*)_t; }
    int *p_nb, *p_nb1, *p_nb2, *p_nbp1, *p_nbp2, *p_n1, *p_n2;
    SYMI(p_nb, g_nb); SYMI(p_nb1, g_nb1); SYMI(p_nb2, g_nb2);
    SYMI(p_nbp1, g_nbp1); SYMI(p_nbp2, g_nbp2); SYMI(p_n1, g_n1); SYMI(p_n2, g_n2);
    float *p_fm0, *p_fo1, *p_cv1, *p_fm1, *p_fp1, *p_fo2, *p_cv2, *p_fm2;
    float *p_fo3, *p_cv3, *p_fm3, *p_fp2, *p_fo4, *p_fm4, *p_fg;
    float *p_f01, *p_f23, *p_pA, *p_pB, *p_pC, *p_pDE;
    float *p_h1, *p_h2, *p_acc;
    SYMF(p_fm0, g_fm0); SYMF(p_fo1, g_fo1); SYMF(p_cv1, g_cv1); SYMF(p_fm1, g_fm1);
    SYMF(p_fp1, g_fp1); SYMF(p_fo2, g_fo2); SYMF(p_cv2, g_cv2); SYMF(p_fm2, g_fm2);
    SYMF(p_fo3, g_fo3); SYMF(p_cv3, g_cv3); SYMF(p_fm3, g_fm3); SYMF(p_fp2, g_fp2);
    SYMF(p_fo4, g_fo4); SYMF(p_fm4, g_fm4); SYMF(p_fg, g_fg);
    SYMF(p_f01, g_f01); SYMF(p_f23, g_f23); SYMF(p_pA, g_pA); SYMF(p_pB, g_pB);
    SYMF(p_pC, g_pC); SYMF(p_pDE, g_pDE);
    SYMF(p_h1, g_h1); SYMF(p_h2, g_h2);
    SYMF(p_acc, g_bnacc);
    float* s1 = p_acc;        float* q1 = p_acc + 128;
    float* s2 = p_acc + 256;  float* q2 = p_acc + 512;
    float* s3 = p_acc + 768;  float* q3 = p_acc + 1024;

    // ---------- packed points (+ zero BN accumulators), fork side streams ----------
    k_prep_pts<<<cdiv(BSZ * NV, 256), 256>>>(vertices, p_pts4, p_acc);
    cudaEventRecord(ev_fork, 0);
    cudaStreamWaitEvent(s_a, ev_fork, 0);
    cudaStreamWaitEvent(s_b, ev_fork, 0);

    // s_a: direction norms, nearest indices, then nb1 kNN
    k_norm_all<<<cdiv(8960, 256), 256, 0, s_a>>>(dir0, dir1, dir2, dir3, dir4,
                                                 p_d0, p_d1, p_d2, p_d3, p_d4);
    cudaEventRecord(ev_nm, s_a);
    k_nearest<<<dim3(cdiv(NV, 128), BSZ), 128, 512 * 16, s_a>>>(
        p_pts4, NV, NV, 512, p_n1);
    k_nearest<<<dim3(cdiv(NV, 128), BSZ), 128, 128 * 16, s_a>>>(
        p_pts4, NV, NV, 128, p_n2);
    cudaEventRecord(ev_ja, s_a);
    k_knn<10, 4><<<dim3(512 / 64, BSZ), 256, 512 * 16 + 256 * 10 * 8, s_a>>>(
        p_pts4, NV, 512, 512, p_nb1);
    cudaEventRecord(ev_jn1, s_a);

    // s_b: pooled-graph kNNs (nbp1 now SUB=16)
    k_knn<4, 16><<<dim3(512 / 16, BSZ), 256, NV * 16 + 256 * 4 * 8, s_b>>>(
        p_pts4, NV, NV, 512, p_nbp1);
    k_knn<4, 4><<<dim3(2, BSZ), 256, 512 * 16 + 256 * 4 * 8, s_b>>>(
        p_pts4, NV, 512, 128, p_nbp2);
    k_knn<10, 4><<<dim3(2, BSZ), 256, 128 * 16 + 256 * 10 * 8, s_b>>>(
        p_pts4, NV, 128, 128, p_nb2);
    cudaEventRecord(ev_jb, s_b);

    // main: big kNN, SUB=16
    k_knn<10, 16><<<dim3(NV / 16, BSZ), 256, NV * 16 + 256 * 10 * 8>>>(
        p_pts4, NV, NV, NV, p_nb);

    // ---------- main pipeline ----------
    cudaStreamWaitEvent(0, ev_nm, 0);
    k_conv_surface<<<dim3(NV, BSZ), 128>>>(vertices, p_nb, p_d0, p_fm0, p_f01);

    // layer1
    k_gemm_bf16x3<false, false, true><<<dim3(1024 / 128, BSZ * NV / 128), 256>>>(
        p_fm0, w1, b1, p_fo1, BSZ * NV, 1024, 128, 1024);
    k_conv_layer<<<dim3(NV, BSZ), 128>>>(vertices, NV, NV, p_nb, p_fo1, p_d1, 128, p_cv1);
    k_bn_stats_at<<<dim3(128 / 32, 32), dim3(32, 32)>>>(p_cv1, BSZ * NV, 128, s1, q1);
    k_bn_apply<<<cdiv(BSZ * NV * 128, 256), 256>>>(p_cv1, s1, q1, g_bn1, be_bn1,
                                                   p_f01, BSZ * NV * 128, 128, 256, 128,
                                                   1.f / (BSZ * NV), p_fm1);

    // fork: pA GEMM depends only on f01 (queued on s_a after its graph work)
    cudaEventRecord(ev_bn1, 0);
    cudaStreamWaitEvent(s_a, ev_bn1, 0);
    k_gemm_bf16x3<true, false, false><<<dim3(512 / 128, BSZ * NV / 128), 256, 0, s_a>>>(
        p_f01, wc1, nullptr, p_pA, BSZ * NV, 512, 256, 1808);
    cudaEventRecord(ev_pa, s_a);

    // join pooled kNNs (nbp1/nbp2/nb2) before pool1
    cudaStreamWaitEvent(0, ev_jb, 0);

    // pool1
    k_pool<<<dim3(512, BSZ), 128>>>(p_fm1, NV, p_nbp1, 128, p_fp1);

    // layer2 (conv2 needs nb1 from s_a)
    k_gemm_bf16x3<false, false, true><<<dim3(2048 / 128, BSZ * 512 / 128), 256>>>(
        p_fp1, w2, b2, p_fo2, BSZ * 512, 2048, 128, 2048);
    cudaStreamWaitEvent(0, ev_jn1, 0);
    k_conv_layer<<<dim3(512, BSZ), 256>>>(vertices, NV, 512, p_nb1, p_fo2, p_d2, 256, p_cv2);
    k_bn_stats_at<<<dim3(256 / 32, 8), dim3(32, 32)>>>(p_cv2, BSZ * 512, 256, s2, q2);
    k_bn_apply<<<cdiv(BSZ * 512 * 256, 256), 256>>>(p_cv2, s2, q2, g_bn2, be_bn2,
                                                    p_f23, BSZ * 512 * 256, 256, 512, 0,
                                                    1.f / (BSZ * 512), p_fm2);

    // layer3
    k_gemm_bf16x3<false, false, true><<<dim3(2048 / 128, BSZ * 512 / 128), 256>>>(
        p_fm2, w3, b3, p_fo3, BSZ * 512, 2048, 256, 2048);
    k_conv_layer<<<dim3(512, BSZ), 256>>>(vertices, NV, 512, p_nb1, p_fo3, p_d3, 256, p_cv3);
    k_bn_stats_at<<<dim3(256 / 32, 8), dim3(32, 32)>>>(p_cv3, BSZ * 512, 256, s3, q3);
    k_bn_apply<<<cdiv(BSZ * 512 * 256, 256), 256>>>(p_cv3, s3, q3, g_bn3, be_bn3,
                                                    p_f23, BSZ * 512 * 256, 256, 512, 256,
                                                    1.f / (BSZ * 512), p_fm3);

    // fork: pB GEMM depends only on f23
    cudaEventRecord(ev_bn3, 0);
    cudaStreamWaitEvent(s_b, ev_bn3, 0);
    k_gemm_bf16x3<true, false, false><<<dim3(512 / 128, BSZ * 512 / 128), 256, 0, s_b>>>(
        p_f23, wc1 + 256, nullptr, p_pB, BSZ * 512, 512, 512, 1808);

    // pool2
    k_pool<<<dim3(128, BSZ), 256>>>(p_fm3, 512, p_nbp2, 256, p_fp2);

    // layer4
    k_gemm_bf16x3<false, false, true><<<dim3(4096 / 128, BSZ * 128 / 128), 256>>>(
        p_fp2, w4, b4, p_fo4, BSZ * 128, 4096, 256, 4096);
    k_conv_layer<<<dim3(128, BSZ), 512>>>(vertices, NV, 128, p_nb2, p_fo4, p_d4, 512, p_fm4);
    cudaEventRecord(ev_l4, 0);

    // s_a: assemble/feat (needs fm0..fm4, n1, n2)
    cudaStreamWaitEvent(s_a, ev_l4, 0);
    float* feat_out = out + (size_t)BSZ * NV * 6 + (size_t)BSZ * NV * 24;
    k_assemble<<<dim3(NV, BSZ), 256, 0, s_a>>>(p_fm0, p_fm1, p_fm2, p_fm3, p_fm4, onehot,
                                               p_n1, p_n2, feat_out);
    cudaEventRecord(ev_asm, s_a);

    // s_b: pC (after pB, after l4)
    cudaStreamWaitEvent(s_b, ev_l4, 0);
    k_gemm_bf16x3<true, false, false><<<dim3(512 / 128, BSZ * 128 / 128), 256, 0, s_b>>>(
        p_fm4, wc1 + 768, nullptr, p_pC, BSZ * 128, 512, 512, 1808);
    cudaEventRecord(ev_pc, s_b);

    // main: fglobal + pde (overlap with pC on s_b, assemble on s_a)
    k_fglobal<<<BSZ, 512>>>(p_fm4, p_fg);
    k_pde<<<dim3(64, BSZ), 256>>>(p_fg, onehot, wc1, bc1, p_pDE);

    // join pA, pB+pC, n1/n2 then combine
    cudaStreamWaitEvent(0, ev_pa, 0);
    cudaStreamWaitEvent(0, ev_pc, 0);
    cudaStreamWaitEvent(0, ev_ja, 0);
    k_combine<<<BSZ * NV, 128>>>(p_pA, p_pB, p_pC, p_pDE, p_n1, p_n2, p_h1);

    // rest of MLP; head writes seg/vecs directly into d_out
    k_gemm_bf16x3<true, true, true><<<dim3(512 / 128, BSZ * NV / 128), 256>>>(
        p_h1, wc2, bc2, p_h2, BSZ * NV, 512, 512, 512);
    k_gemm_head<<<dim3(1, BSZ * NV / BM), 256>>>(p_h2, wc3, bc3, out, BSZ * NV, 512);

    // join assemble before returning
    cudaStreamWaitEvent(0, ev_asm, 0);
}

// round 17
// speedup vs baseline: 1.0306x; 1.0306x over previous
#include <cuda_runtime.h>
#include <cuda_bf16.h>
#include <math.h>

// ---------------- problem constants ----------------
#define BSZ 4
#define NV  2048

// ---------------- device scratch ----------------
__device__ float g_d0[3*896];
__device__ float g_d1[3*896];
__device__ float g_d2[3*1792];
__device__ float g_d3[3*1792];
__device__ float g_d4[3*3584];

__device__ float4 g_pts4[BSZ*NV];

__device__ int   g_nb  [BSZ*NV*10];
__device__ int   g_nb1 [BSZ*512*10];
__device__ int   g_nb2 [BSZ*128*10];
__device__ int   g_nbp1[BSZ*512*4];
__device__ int   g_nbp2[BSZ*128*4];
__device__ int   g_n1  [BSZ*NV];
__device__ int   g_n2  [BSZ*NV];

__device__ float g_fm0[BSZ*NV*128];
__device__ float g_fo1[BSZ*NV*1024];
__device__ float g_cv1[BSZ*NV*128];
__device__ float g_fm1[BSZ*NV*128];
__device__ float g_fp1[BSZ*512*128];
__device__ float g_fo2[BSZ*512*2048];
__device__ float g_cv2[BSZ*512*256];
__device__ float g_fm2[BSZ*512*256];
__device__ float g_fo3[BSZ*512*2048];
__device__ float g_cv3[BSZ*512*256];
__device__ float g_fm3[BSZ*512*256];
__device__ float g_fp2[BSZ*128*256];
__device__ float g_fo4[BSZ*128*4096];
__device__ float g_fm4[BSZ*128*512];
__device__ float g_fg [BSZ*512];
__device__ float g_f01[BSZ*NV*256];
__device__ float g_f23[BSZ*512*512];
__device__ float g_pA [BSZ*NV*512];
__device__ float g_pB [BSZ*512*512];
__device__ float g_pC [BSZ*128*512];
__device__ float g_pDE[BSZ*512];
__device__ float g_h1 [BSZ*NV*512];
__device__ float g_h2 [BSZ*NV*512];
// BN accumulators: [s1 128 | q1 128 | s2 256 | q2 256 | s3 256 | q3 256]
__device__ float g_bnacc[1280];

// ---------------- kNN (dot-product form, packed float4 points) ----------------
template <int KN, int SUB>
__global__ void k_knn(const float4* __restrict__ pts4, int bstride, int N, int Q,
                      int* __restrict__ out) {
    extern __shared__ float4 sp4[];
    float* smd = (float*)(sp4 + N);
    int* smi = (int*)(smd + 256 * KN);
    const int QPB = 256 / SUB;
    int b = blockIdx.y;
    const float4* P = pts4 + (size_t)b * bstride;
    for (int i = threadIdx.x; i < N; i += blockDim.x) sp4[i] = P[i];
    __syncthreads();
    int sub = threadIdx.x % SUB;
    int ql = threadIdx.x / SUB;
    int q = blockIdx.x * QPB + ql;
    float bd[KN]; int bi[KN];
#pragma unroll
    for (int i = 0; i < KN; i++) { bd[i] = 3.4e38f; bi[i] = 0x7fffffff; }
    if (q < Q) {
        float4 qp = sp4[q];
        float nqx = -2.f * qp.x, nqy = -2.f * qp.y, nqz = -2.f * qp.z;
#pragma unroll 4
        for (int j = sub; j < N; j += SUB) {
            float4 p = sp4[j];
            float d = fmaf(p.x, nqx, fmaf(p.y, nqy, fmaf(p.z, nqz, p.w)));
            if (d < bd[KN - 1] && j != q) {
                bd[KN - 1] = d; bi[KN - 1] = j;
#pragma unroll
                for (int r = KN - 1; r > 0; --r) {
                    if (bd[r] < bd[r - 1]) {
                        float td = bd[r]; bd[r] = bd[r - 1]; bd[r - 1] = td;
                        int ti = bi[r]; bi[r] = bi[r - 1]; bi[r - 1] = ti;
                    }
                }
            }
        }
    }
    int base = threadIdx.x * KN;
#pragma unroll
    for (int i = 0; i < KN; i++) { smd[base + i] = bd[i]; smi[base + i] = bi[i]; }
    if (SUB > 4) __syncthreads(); else __syncwarp();
    if (sub == 0 && q < Q) {
        int p[SUB];
#pragma unroll
        for (int l = 0; l < SUB; l++) p[l] = 0;
        int lbase = ql * SUB * KN;
        int* o = out + ((size_t)b * Q + q) * KN;
#pragma unroll
        for (int k = 0; k < KN; k++) {
            float best = 3.5e38f; int bidx = 0x7fffffff; int bl = 0;
#pragma unroll
            for (int l = 0; l < SUB; l++) {
                int pp = p[l];
                float d = (pp < KN) ? smd[lbase + l * KN + pp] : 3.6e38f;
                int ix = (pp < KN) ? smi[lbase + l * KN + pp] : 0x7fffffff;
                if (d < best || (d == best && ix < bidx)) { best = d; bidx = ix; bl = l; }
            }
            p[bl]++;
            o[k] = bidx;
        }
    }
}

__global__ void k_nearest(const float4* __restrict__ pts4, int bstride, int Nt, int Ns,
                          int* __restrict__ out) {
    extern __shared__ float4 sp4[];
    int b = blockIdx.y;
    const float4* P = pts4 + (size_t)b * bstride;
    for (int i = threadIdx.x; i < Ns; i += blockDim.x) sp4[i] = P[i];
    __syncthreads();
    int t = blockIdx.x * blockDim.x + threadIdx.x;
    if (t >= Nt) return;
    float4 qp = pts4[(size_t)b * bstride + t];
    float nqx = -2.f * qp.x, nqy = -2.f * qp.y, nqz = -2.f * qp.z;
    float best = 3.4e38f; int bi = 0;
#pragma unroll 4
    for (int j = 0; j < Ns; j++) {
        float4 p = sp4[j];
        float d = fmaf(p.x, nqx, fmaf(p.y, nqy, fmaf(p.z, nqz, p.w)));
        if (d < best) { best = d; bi = j; }
    }
    out[(size_t)b * Nt + t] = bi;
}

// ---------------- streams/events ----------------
static cudaStream_t s_a = 0, s_b = 0;
static cudaEvent_t ev_fork, ev_nm, ev_ja, ev_jb, ev_bn1, ev_pa, ev_bn3, ev_pb, ev_l4, ev_asm;

struct _StreamInit {
    _StreamInit() {
        cudaStreamCreateWithFlags(&s_a, cudaStreamNonBlocking);
        cudaStreamCreateWithFlags(&s_b, cudaStreamNonBlocking);
        cudaEventCreateWithFlags(&ev_fork, cudaEventDisableTiming);
        cudaEventCreateWithFlags(&ev_nm, cudaEventDisableTiming);
        cudaEventCreateWithFlags(&ev_ja, cudaEventDisableTiming);
        cudaEventCreateWithFlags(&ev_jb, cudaEventDisableTiming);
        cudaEventCreateWithFlags(&ev_bn1, cudaEventDisableTiming);
        cudaEventCreateWithFlags(&ev_pa, cudaEventDisableTiming);
        cudaEventCreateWithFlags(&ev_bn3, cudaEventDisableTiming);
        cudaEventCreateWithFlags(&ev_pb, cudaEventDisableTiming);
        cudaEventCreateWithFlags(&ev_l4, cudaEventDisableTiming);
        cudaEventCreateWithFlags(&ev_asm, cudaEventDisableTiming);
        cudaFuncSetAttribute(k_knn<10, 16>, cudaFuncAttributeMaxDynamicSharedMemorySize,
                             NV * 16 + 256 * 10 * 8);
        cudaFuncSetAttribute(k_knn<4, 16>, cudaFuncAttributeMaxDynamicSharedMemorySize,
                             NV * 16 + 256 * 4 * 8);
        cudaFuncSetAttribute(k_knn<10, 8>, cudaFuncAttributeMaxDynamicSharedMemorySize,
                             NV * 16 + 256 * 10 * 8);
        cudaFuncSetAttribute(k_knn<4, 8>, cudaFuncAttributeMaxDynamicSharedMemorySize,
                             NV * 16 + 256 * 4 * 8);
    }
};
static _StreamInit g_stream_init;

// ---------------- misc kernels ----------------

__global__ void k_prep_pts(const float* __restrict__ verts, float4* __restrict__ pts4,
                           float* __restrict__ bnacc) {
    int i = blockIdx.x * blockDim.x + threadIdx.x;
    if (i < 1280) bnacc[i] = 0.f;
    if (i >= BSZ * NV) return;
    float x = verts[i * 3], y = verts[i * 3 + 1], z = verts[i * 3 + 2];
    pts4[i] = make_float4(x, y, z, x * x + y * y + z * z);
}

__global__ void k_norm_all(const float* __restrict__ d0, const float* __restrict__ d1,
                           const float* __restrict__ d2, const float* __restrict__ d3,
                           const float* __restrict__ d4,
                           float* __restrict__ o0, float* __restrict__ o1,
                           float* __restrict__ o2, float* __restrict__ o3,
                           float* __restrict__ o4) {
    int i = blockIdx.x * blockDim.x + threadIdx.x;
    const float* src; float* dst; int D, c;
    if (i < 896)        { src = d0; dst = o0; D = 896;  c = i; }
    else if (i < 1792)  { src = d1; dst = o1; D = 896;  c = i - 896; }
    else if (i < 3584)  { src = d2; dst = o2; D = 1792; c = i - 1792; }
    else if (i < 5376)  { src = d3; dst = o3; D = 1792; c = i - 3584; }
    else if (i < 8960)  { src = d4; dst = o4; D = 3584; c = i - 5376; }
    else return;
    float x = src[c], y = src[D + c], z = src[2 * D + c];
    float inv = 1.f / fmaxf(sqrtf(x * x + y * y + z * z), 1e-12f);
    dst[c] = x * inv; dst[D + c] = y * inv; dst[2 * D + c] = z * inv;
}

__global__ void k_conv_surface(const float* __restrict__ verts, const int* __restrict__ nb,
                               const float* __restrict__ sd, float* __restrict__ out,
                               float* __restrict__ f01) {
    int b = blockIdx.y, v = blockIdx.x;
    __shared__ float nd[10][3];
    size_t row = (size_t)b * NV + v;
    if (threadIdx.x < 10) {
        int j = nb[row * 10 + threadIdx.x];
        const float* c0 = verts + row * 3;
        const float* c1 = verts + ((size_t)b * NV + j) * 3;
        float dx = c1[0] - c0[0], dy = c1[1] - c0[1], dz = c1[2] - c0[2];
        float inv = 1.f / fmaxf(sqrtf(dx * dx + dy * dy + dz * dz), 1e-12f);
        nd[threadIdx.x][0] = dx * inv; nd[threadIdx.x][1] = dy * inv; nd[threadIdx.x][2] = dz * inv;
    }
    __syncthreads();
    int c = threadIdx.x;
    float acc = 0.f;
#pragma unroll
    for (int s = 0; s < 7; s++) {
        int col = s * 128 + c;
        float sx = sd[col], sy = sd[896 + col], sz = sd[1792 + col];
        float m = 0.f;
#pragma unroll
        for (int n = 0; n < 10; n++) {
            float t = nd[n][0] * sx + nd[n][1] * sy + nd[n][2] * sz;
            m = fmaxf(m, t);
        }
        acc += m;
    }
    float r = fmaxf(acc, 0.f);
    out[row * 128 + c] = r;
    f01[row * 256 + c] = r;
}

__global__ void k_conv_layer(const float* __restrict__ verts, int vstride, int V,
                             const int* __restrict__ nb, const float* __restrict__ fo,
                             const float* __restrict__ sd, int OC, float* __restrict__ out) {
    int b = blockIdx.y, v = blockIdx.x;
    __shared__ float nd[10][3];
    __shared__ int nidx[10];
    if (threadIdx.x < 10) {
        int j = nb[((size_t)b * V + v) * 10 + threadIdx.x];
        nidx[threadIdx.x] = j;
        const float* c0 = verts + ((size_t)b * vstride + v) * 3;
        const float* c1 = verts + ((size_t)b * vstride + j) * 3;
        float dx = c1[0] - c0[0], dy = c1[1] - c0[1], dz = c1[2] - c0[2];
        float inv = 1.f / fmaxf(sqrtf(dx * dx + dy * dy + dz * dz), 1e-12f);
        nd[threadIdx.x][0] = dx * inv; nd[threadIdx.x][1] = dy * inv; nd[threadIdx.x][2] = dz * inv;
    }
    __syncthreads();
    int c = threadIdx.x;
    int FW = 8 * OC, D = 7 * OC;
    const float* base = fo + (size_t)b * V * FW;
    float acc = base[(size_t)v * FW + c];
#pragma unroll
    for (int s = 0; s < 7; s++) {
        int col = s * OC + c;
        float sx = sd[col], sy = sd[D + col], sz = sd[2 * D + col];
        float m = -3.4e38f;
#pragma unroll
        for (int n = 0; n < 10; n++) {
            float t = fmaxf(nd[n][0] * sx + nd[n][1] * sy + nd[n][2] * sz, 0.f);
            float sup = base[(size_t)nidx[n] * FW + OC + col];
            m = fmaxf(m, t * sup);
        }
        acc += m;
    }
    out[((size_t)b * V + v) * OC + c] = acc;
}

__global__ void k_bn_stats_at(const float* __restrict__ x, int R, int C,
                              float* __restrict__ sum, float* __restrict__ sq) {
    int c = blockIdx.x * 32 + threadIdx.x;
    int rows = R / gridDim.y;
    int r0 = blockIdx.y * rows;
    float s = 0.f, s2 = 0.f;
    for (int r = r0 + threadIdx.y; r < r0 + rows; r += 32) {
        float v = x[(size_t)r * C + c];
        s += v; s2 += v * v;
    }
    __shared__ float sh[32][33], sh2[32][33];
    sh[threadIdx.y][threadIdx.x] = s; sh2[threadIdx.y][threadIdx.x] = s2;
    __syncthreads();
    if (threadIdx.y == 0) {
        float ts = 0.f, ts2 = 0.f;
#pragma unroll
        for (int y = 0; y < 32; y++) { ts += sh[y][threadIdx.x]; ts2 += sh2[y][threadIdx.x]; }
        atomicAdd(&sum[c], ts);
        atomicAdd(&sq[c], ts2);
    }
}

__global__ void k_bn_apply(const float* __restrict__ x, const float* __restrict__ sum,
                           const float* __restrict__ sq, const float* __restrict__ g,
                           const float* __restrict__ be, float* __restrict__ y,
                           int total, int C, int Cy, int coff, float Rinv,
                           float* __restrict__ y2) {
    int i = blockIdx.x * blockDim.x + threadIdx.x;
    if (i >= total) return;
    int c = i % C;
    int r = i / C;
    float m = sum[c] * Rinv;
    float var = sq[c] * Rinv - m * m;
    float v = (x[i] - m) * rsqrtf(var + 1e-5f) * g[c] + be[c];
    v = fmaxf(v, 0.f);
    y[(size_t)r * Cy + coff + c] = v;
    if (y2) y2[i] = v;
}

__global__ void k_pool(const float* __restrict__ fm, int Vin, const int* __restrict__ nbp,
                       int C, float* __restrict__ out) {
    int b = blockIdx.y, p = blockIdx.x, c = threadIdx.x;
    int P = gridDim.x;
    const int* nr = nbp + ((size_t)b * P + p) * 4;
    float m = -3.4e38f;
#pragma unroll
    for (int j = 0; j < 4; j++)
        m = fmaxf(m, fm[((size_t)b * Vin + nr[j]) * C + c]);
    out[((size_t)b * P + p) * C + c] = m;
}

__global__ void k_fglobal(const float* __restrict__ fm4, float* __restrict__ fg) {
    int b = blockIdx.x, c = threadIdx.x;
    float m = -3.4e38f;
    for (int r = 0; r < 128; r++)
        m = fmaxf(m, fm4[((size_t)b * 128 + r) * 512 + c]);
    fg[b * 512 + c] = m;
}

__global__ void k_assemble(const float* __restrict__ fm0, const float* __restrict__ fm1,
                           const float* __restrict__ fm2, const float* __restrict__ fm3,
                           const float* __restrict__ fm4, const float* __restrict__ onehot,
                           const int* __restrict__ n1, const int* __restrict__ n2,
                           float* __restrict__ feat) {
    int b = blockIdx.y, v = blockIdx.x;
    size_t row = (size_t)b * NV + v;
    int i1 = n1[row], i2 = n2[row];
    float* fe = feat + row * 1296;
    for (int c = threadIdx.x; c < 1296; c += blockDim.x) {
        float val;
        if (c < 128)        val = fm0[row * 128 + c];
        else if (c < 256)   val = fm1[row * 128 + (c - 128)];
        else if (c < 512)   val = fm2[((size_t)b * 512 + i1) * 256 + (c - 256)];
        else if (c < 768)   val = fm3[((size_t)b * 512 + i1) * 256 + (c - 512)];
        else if (c < 1280)  val = fm4[((size_t)b * 128 + i2) * 512 + (c - 768)];
        else                val = onehot[b * 16 + (c - 1280)];
        fe[c] = val;
    }
}

__global__ void k_pde(const float* __restrict__ fg, const float* __restrict__ onehot,
                      const float* __restrict__ wc1, const float* __restrict__ bc1,
                      float* __restrict__ pde) {
    int b = blockIdx.y;
    int o = blockIdx.x * 8 + (threadIdx.x >> 5);
    int lane = threadIdx.x & 31;
    const float* w = wc1 + (size_t)o * 1808;
    float s = 0.f;
    for (int c = lane; c < 512; c += 32) s = fmaf(fg[b * 512 + c], w[1280 + c], s);
    if (lane < 16) s = fmaf(onehot[b * 16 + lane], w[1792 + lane], s);
#pragma unroll
    for (int off = 16; off; off >>= 1) s += __shfl_down_sync(0xffffffffu, s, off);
    if (lane == 0) pde[b * 512 + o] = s + bc1[o];
}

__global__ void k_combine(const float* __restrict__ pA, const float* __restrict__ pB,
                          const float* __restrict__ pC, const float* __restrict__ pDE,
                          const int* __restrict__ n1, const int* __restrict__ n2,
                          float* __restrict__ h1) {
    int row = blockIdx.x;
    int b = row >> 11;
    int i1 = n1[row], i2 = n2[row];
    const float4* a  = (const float4*)(pA + (size_t)row * 512);
    const float4* pb = (const float4*)(pB + ((size_t)b * 512 + i1) * 512);
    const float4* pc = (const float4*)(pC + ((size_t)b * 128 + i2) * 512);
    const float4* pd = (const float4*)(pDE + (size_t)b * 512);
    float4* o = (float4*)(h1 + (size_t)row * 512);
    for (int c = threadIdx.x; c < 128; c += blockDim.x) {
        float4 va = a[c], vb = pb[c], vc = pc[c], vd = pd[c];
        float4 r;
        r.x = fmaxf(va.x + vb.x + vc.x + vd.x, 0.f);
        r.y = fmaxf(va.y + vb.y + vc.y + vd.y, 0.f);
        r.z = fmaxf(va.z + vb.z + vc.z + vd.z, 0.f);
        r.w = fmaxf(va.w + vb.w + vc.w + vd.w, 0.f);
        o[c] = r;
    }
}

// ---------------- 3xBF16 tensor-core GEMM ----------------
__device__ __forceinline__ void split_bf16_pair(float x0, float x1,
                                                unsigned& hi, unsigned& lo) {
    __nv_bfloat162 h = __floats2bfloat162_rn(x0, x1);
    float r0 = x0 - __bfloat162float(h.x);
    float r1 = x1 - __bfloat162float(h.y);
    __nv_bfloat162 l = __floats2bfloat162_rn(r0, r1);
    hi = *reinterpret_cast<unsigned*>(&h);
    lo = *reinterpret_cast<unsigned*>(&l);
}

#define MMA16(acc, a0, a1, a2, a3, b0, b1)                                    \
    asm volatile(                                                             \
        "mma.sync.aligned.m16n8k16.row.col.f32.bf16.bf16.f32 "                \
        "{%0,%1,%2,%3}, {%4,%5,%6,%7}, {%8,%9}, {%0,%1,%2,%3};\n"             \
        : "+f"(acc[0]), "+f"(acc[1]), "+f"(acc[2]), "+f"(acc[3])              \
        : "r"(a0), "r"(a1), "r"(a2), "r"(a3), "r"(b0), "r"(b1))

template <bool BT, bool RELU, bool BIAS>
__global__ void __launch_bounds__(256)
k_gemm_bf16x3(const float* __restrict__ A, const float* __restrict__ B,
              const float* __restrict__ bias, float* __restrict__ C,
              int M, int N, int K, int ldb) {
    __shared__ unsigned Ah[8][136], Al[8][136];
    __shared__ unsigned Bh[8][136], Bl[8][136];
    int tid = threadIdx.x;
    int lane = tid & 31, warp = tid >> 5;
    int wm = (warp & 1) * 64, wn = (warp >> 1) * 32;
    int bm = blockIdx.y * 128, bn = blockIdx.x * 128;

    float acc[4][4][4];
#pragma unroll
    for (int i = 0; i < 4; i++)
#pragma unroll
        for (int j = 0; j < 4; j++)
#pragma unroll
            for (int k = 0; k < 4; k++) acc[i][j][k] = 0.f;

    float4 pa[2];
    float4 pbt[2];
    float2 pbn0[2], pbn1[2];

#define LOAD_AB(k0)                                                             \
    _Pragma("unroll")                                                           \
    for (int i = 0; i < 2; i++) {                                               \
        int idx = tid + i * 256;                                                \
        pa[i] = *reinterpret_cast<const float4*>(                               \
            A + (size_t)(bm + (idx & 127)) * K + (k0) + (idx >> 7) * 4);        \
        if (BT) {                                                               \
            pbt[i] = *reinterpret_cast<const float4*>(                          \
                B + (size_t)(bn + (idx & 127)) * ldb + (k0) + (idx >> 7) * 4);  \
        } else {                                                                \
            int pr = idx >> 6, n2 = (idx & 63) * 2;                             \
            pbn0[i] = *reinterpret_cast<const float2*>(                         \
                B + (size_t)((k0) + 2 * pr) * ldb + bn + n2);                   \
            pbn1[i] = *reinterpret_cast<const float2*>(                         \
                B + (size_t)((k0) + 2 * pr + 1) * ldb + bn + n2);               \
        }                                                                       \
    }
#define STORE_AB()                                                              \
    _Pragma("unroll")                                                           \
    for (int i = 0; i < 2; i++) {                                               \
        int idx = tid + i * 256;                                                \
        int ar = idx & 127, apr = (idx >> 7) * 2;                               \
        split_bf16_pair(pa[i].x, pa[i].y, Ah[apr][ar], Al[apr][ar]);            \
        split_bf16_pair(pa[i].z, pa[i].w, Ah[apr + 1][ar], Al[apr + 1][ar]);    \
        if (BT) {                                                               \
            split_bf16_pair(pbt[i].x, pbt[i].y, Bh[apr][ar], Bl[apr][ar]);      \
            split_bf16_pair(pbt[i].z, pbt[i].w, Bh[apr + 1][ar], Bl[apr + 1][ar]); \
        } else {                                                                \
            int pr = idx >> 6, n2 = (idx & 63) * 2;                             \
            split_bf16_pair(pbn0[i].x, pbn1[i].x, Bh[pr][n2], Bl[pr][n2]);      \
            split_bf16_pair(pbn0[i].y, pbn1[i].y, Bh[pr][n2 + 1], Bl[pr][n2 + 1]); \
        }                                                                       \
    }

    LOAD_AB(0);
    STORE_AB();
    __syncthreads();

    int r = lane >> 2, cq = lane & 3;
    int nT = K / 16;
    for (int t = 0; t < nT; t++) {
        if (t + 1 < nT) {
            int k0 = (t + 1) * 16;
            LOAD_AB(k0);
        }
        unsigned afh[4][4], afl[4][4], bfh[4][2], bfl[4][2];
#pragma unroll
        for (int mf = 0; mf < 4; mf++) {
            int m0 = wm + mf * 16 + r;
            afh[mf][0] = Ah[cq][m0];         afl[mf][0] = Al[cq][m0];
            afh[mf][1] = Ah[cq][m0 + 8];     afl[mf][1] = Al[cq][m0 + 8];
            afh[mf][2] = Ah[cq + 4][m0];     afl[mf][2] = Al[cq + 4][m0];
            afh[mf][3] = Ah[cq + 4][m0 + 8]; afl[mf][3] = Al[cq + 4][m0 + 8];
        }
#pragma unroll
        for (int nf = 0; nf < 4; nf++) {
            int n0 = wn + nf * 8 + r;
            bfh[nf][0] = Bh[cq][n0];     bfl[nf][0] = Bl[cq][n0];
            bfh[nf][1] = Bh[cq + 4][n0]; bfl[nf][1] = Bl[cq + 4][n0];
        }
#pragma unroll
        for (int mf = 0; mf < 4; mf++)
#pragma unroll
            for (int nf = 0; nf < 4; nf++) {
                MMA16(acc[mf][nf], afh[mf][0], afh[mf][1], afh[mf][2], afh[mf][3],
                      bfl[nf][0], bfl[nf][1]);
                MMA16(acc[mf][nf], afl[mf][0], afl[mf][1], afl[mf][2], afl[mf][3],
                      bfh[nf][0], bfh[nf][1]);
                MMA16(acc[mf][nf], afh[mf][0], afh[mf][1], afh[mf][2], afh[mf][3],
                      bfh[nf][0], bfh[nf][1]);
            }
        if (t + 1 < nT) {
            __syncthreads();
            STORE_AB();
            __syncthreads();
        }
    }

    int c2 = (lane & 3) * 2;
#pragma unroll
    for (int nf = 0; nf < 4; nf++) {
        int col = bn + wn + nf * 8 + c2;
        float b0 = BIAS ? bias[col] : 0.f;
        float b1 = BIAS ? bias[col + 1] : 0.f;
#pragma unroll
        for (int mf = 0; mf < 4; mf++) {
            int row0 = bm + wm + mf * 16 + r;
            float v0 = acc[mf][nf][0] + b0, v1 = acc[mf][nf][1] + b1;
            float v2 = acc[mf][nf][2] + b0, v3 = acc[mf][nf][3] + b1;
            if (RELU) {
                v0 = fmaxf(v0, 0.f); v1 = fmaxf(v1, 0.f);
                v2 = fmaxf(v2, 0.f); v3 = fmaxf(v3, 0.f);
            }
            *reinterpret_cast<float2*>(&C[(size_t)row0 * N + col]) = make_float2(v0, v1);
            *reinterpret_cast<float2*>(&C[(size_t)(row0 + 8) * N + col]) = make_float2(v2, v3);
        }
    }
#undef LOAD_AB
#undef STORE_AB
}

// head GEMM (N=30) fused with seg/vecs split into d_out
#define BM 64
#define BN 64
#define BKK 16
__global__ void k_gemm_head(const float* __restrict__ A, const float* __restrict__ B,
                            const float* __restrict__ bias, float* __restrict__ out,
                            int M, int K) {
    const int N = 30;
    __shared__ __align__(16) float As[BKK][BM + 4];
    __shared__ __align__(16) float Bs[BKK][BN + 4];
    int bm = blockIdx.y * BM;
    int tid = threadIdx.x;
    int tx = tid & 15, ty = tid >> 4;
    float acc[4][4] = {};
    for (int k0 = 0; k0 < K; k0 += BKK) {
#pragma unroll
        for (int i = 0; i < 4; i++) {
            int idx = tid + i * 256;
            int r = idx >> 4, kk = idx & 15;
            As[kk][r] = A[(size_t)(bm + r) * K + k0 + kk];
        }
#pragma unroll
        for (int i = 0; i < 4; i++) {
            int idx = tid + i * 256;
            int n = idx >> 4, kk = idx & 15;
            Bs[kk][n] = (n < N) ? B[(size_t)n * K + k0 + kk] : 0.f;
        }
        __syncthreads();
#pragma unroll
        for (int kk = 0; kk < BKK; kk++) {
            float4 av = *reinterpret_cast<const float4*>(&As[kk][ty * 4]);
            float4 bv = *reinterpret_cast<const float4*>(&Bs[kk][tx * 4]);
            float a[4] = {av.x, av.y, av.z, av.w};
            float bb[4] = {bv.x, bv.y, bv.z, bv.w};
#pragma unroll
            for (int i = 0; i < 4; i++)
#pragma unroll
                for (int j = 0; j < 4; j++)
                    acc[i][j] += a[i] * bb[j];
        }
        __syncthreads();
    }
    size_t voff = (size_t)BSZ * NV * 6;
#pragma unroll
    for (int i = 0; i < 4; i++) {
        int gr = bm + ty * 4 + i;
#pragma unroll
        for (int j = 0; j < 4; j++) {
            int gn = tx * 4 + j;
            if (gn >= N) continue;
            float v = acc[i][j] + bias[gn];
            if (gn < 6)
                out[(size_t)gr * 6 + gn] = v;
            else
                out[voff + (size_t)gr * 24 + (gn - 6)] = v;
        }
    }
}

// ---------------- host ----------------
static inline int cdiv(int a, int b) { return (a + b - 1) / b; }

#define SYMF(p, s) do { void* _t; cudaGetSymbolAddress(&_t, s); p = (float*)_t; } while (0)
#define SYMI(p, s) do { void* _t; cudaGetSymbolAddress(&_t, s); p = (int*)_t; } while (0)

extern "C" void kernel_launch(void* const* d_in, const int* in_sizes, int n_in,
                              void* d_out, int out_size) {
    const float* vertices = (const float*)d_in[0];
    const float* onehot   = (const float*)d_in[1];
    const float* dir0 = (const float*)d_in[2];
    const float* w1   = (const float*)d_in[3];
    const float* b1   = (const float*)d_in[4];
    const float* dir1 = (const float*)d_in[5];
    const float* w2   = (const float*)d_in[6];
    const float* b2   = (const float*)d_in[7];
    const float* dir2 = (const float*)d_in[8];
    const float* w3   = (const float*)d_in[9];
    const float* b3   = (const float*)d_in[10];
    const float* dir3 = (const float*)d_in[11];
    const float* w4   = (const float*)d_in[12];
    const float* b4   = (const float*)d_in[13];
    const float* dir4 = (const float*)d_in[14];
    const float* g_bn1 = (const float*)d_in[15];
    const float* be_bn1 = (const float*)d_in[16];
    const float* g_bn2 = (const float*)d_in[17];
    const float* be_bn2 = (const float*)d_in[18];
    const float* g_bn3 = (const float*)d_in[19];
    const float* be_bn3 = (const float*)d_in[20];
    const float* wc1 = (const float*)d_in[21];
    const float* bc1 = (const float*)d_in[22];
    const float* wc2 = (const float*)d_in[23];
    const float* bc2 = (const float*)d_in[24];
    const float* wc3 = (const float*)d_in[25];
    const float* bc3 = (const float*)d_in[26];
    float* out = (float*)d_out;

    float *p_d0, *p_d1, *p_d2, *p_d3, *p_d4;
    SYMF(p_d0, g_d0); SYMF(p_d1, g_d1); SYMF(p_d2, g_d2); SYMF(p_d3, g_d3); SYMF(p_d4, g_d4);
    float4* p_pts4; { void* _t; cudaGetSymbolAddress(&_t, g_pts4); p_pts4 = (float4*)_t; }
    int *p_nb, *p_nb1, *p_nb2, *p_nbp1, *p_nbp2, *p_n1, *p_n2;
    SYMI(p_nb, g_nb); SYMI(p_nb1, g_nb1); SYMI(p_nb2, g_nb2);
    SYMI(p_nbp1, g_nbp1); SYMI(p_nbp2, g_nbp2); SYMI(p_n1, g_n1); SYMI(p_n2, g_n2);
    float *p_fm0, *p_fo1, *p_cv1, *p_fm1, *p_fp1, *p_fo2, *p_cv2, *p_fm2;
    float *p_fo3, *p_cv3, *p_fm3, *p_fp2, *p_fo4, *p_fm4, *p_fg;
    float *p_f01, *p_f23, *p_pA, *p_pB, *p_pC, *p_pDE;
    float *p_h1, *p_h2, *p_acc;
    SYMF(p_fm0, g_fm0); SYMF(p_fo1, g_fo1); SYMF(p_cv1, g_cv1); SYMF(p_fm1, g_fm1);
    SYMF(p_fp1, g_fp1); SYMF(p_fo2, g_fo2); SYMF(p_cv2, g_cv2); SYMF(p_fm2, g_fm2);
    SYMF(p_fo3, g_fo3); SYMF(p_cv3, g_cv3); SYMF(p_fm3, g_fm3); SYMF(p_fp2, g_fp2);
    SYMF(p_fo4, g_fo4); SYMF(p_fm4, g_fm4); SYMF(p_fg, g_fg);
    SYMF(p_f01, g_f01); SYMF(p_f23, g_f23); SYMF(p_pA, g_pA); SYMF(p_pB, g_pB);
    SYMF(p_pC, g_pC); SYMF(p_pDE, g_pDE);
    SYMF(p_h1, g_h1); SYMF(p_h2, g_h2);
    SYMF(p_acc, g_bnacc);
    float* s1 = p_acc;        float* q1 = p_acc + 128;
    float* s2 = p_acc + 256;  float* q2 = p_acc + 512;
    float* s3 = p_acc + 768;  float* q3 = p_acc + 1024;

    // ---------- packed points (+ zero BN accumulators), fork side streams ----------
    k_prep_pts<<<cdiv(BSZ * NV, 256), 256>>>(vertices, p_pts4, p_acc);
    cudaEventRecord(ev_fork, 0);
    cudaStreamWaitEvent(s_a, ev_fork, 0);
    cudaStreamWaitEvent(s_b, ev_fork, 0);

    // s_a: direction norms (needed by conv_surface), then nearest indices
    k_norm_all<<<cdiv(8960, 256), 256, 0, s_a>>>(dir0, dir1, dir2, dir3, dir4,
                                                 p_d0, p_d1, p_d2, p_d3, p_d4);
    cudaEventRecord(ev_nm, s_a);
    k_nearest<<<dim3(cdiv(NV, 128), BSZ), 128, 512 * 16, s_a>>>(
        p_pts4, NV, NV, 512, p_n1);
    k_nearest<<<dim3(cdiv(NV, 128), BSZ), 128, 128 * 16, s_a>>>(
        p_pts4, NV, NV, 128, p_n2);
    cudaEventRecord(ev_ja, s_a);

    // s_b: pooled-graph kNNs (nbp1 SUB=16; R14 order otherwise)
    k_knn<4, 16><<<dim3(512 / 16, BSZ), 256, NV * 16 + 256 * 4 * 8, s_b>>>(
        p_pts4, NV, NV, 512, p_nbp1);
    k_knn<10, 4><<<dim3(512 / 64, BSZ), 256, 512 * 16 + 256 * 10 * 8, s_b>>>(
        p_pts4, NV, 512, 512, p_nb1);
    k_knn<4, 4><<<dim3(2, BSZ), 256, 512 * 16 + 256 * 4 * 8, s_b>>>(
        p_pts4, NV, 512, 128, p_nbp2);
    k_knn<10, 4><<<dim3(2, BSZ), 256, 128 * 16 + 256 * 10 * 8, s_b>>>(
        p_pts4, NV, 128, 128, p_nb2);
    cudaEventRecord(ev_jb, s_b);

    // main: big kNN, SUB=16
    k_knn<10, 16><<<dim3(NV / 16, BSZ), 256, NV * 16 + 256 * 10 * 8>>>(
        p_pts4, NV, NV, NV, p_nb);

    // ---------- main pipeline ----------
    cudaStreamWaitEvent(0, ev_nm, 0);
    k_conv_surface<<<dim3(NV, BSZ), 128>>>(vertices, p_nb, p_d0, p_fm0, p_f01);

    // layer1
    k_gemm_bf16x3<false, false, true><<<dim3(1024 / 128, BSZ * NV / 128), 256>>>(
        p_fm0, w1, b1, p_fo1, BSZ * NV, 1024, 128, 1024);
    k_conv_layer<<<dim3(NV, BSZ), 128>>>(vertices, NV, NV, p_nb, p_fo1, p_d1, 128, p_cv1);
    k_bn_stats_at<<<dim3(128 / 32, 32), dim3(32, 32)>>>(p_cv1, BSZ * NV, 128, s1, q1);
    k_bn_apply<<<cdiv(BSZ * NV * 128, 256), 256>>>(p_cv1, s1, q1, g_bn1, be_bn1,
                                                   p_f01, BSZ * NV * 128, 128, 256, 128,
                                                   1.f / (BSZ * NV), p_fm1);

    // fork: pA GEMM depends only on f01
    cudaEventRecord(ev_bn1, 0);
    cudaStreamWaitEvent(s_a, ev_bn1, 0);
    k_gemm_bf16x3<true, false, false><<<dim3(512 / 128, BSZ * NV / 128), 256, 0, s_a>>>(
        p_f01, wc1, nullptr, p_pA, BSZ * NV, 512, 256, 1808);
    cudaEventRecord(ev_pa, s_a);

    // join pooled-graph kNNs
    cudaStreamWaitEvent(0, ev_jb, 0);

    // pool1
    k_pool<<<dim3(512, BSZ), 128>>>(p_fm1, NV, p_nbp1, 128, p_fp1);

    // layer2
    k_gemm_bf16x3<false, false, true><<<dim3(2048 / 128, BSZ * 512 / 128), 256>>>(
        p_fp1, w2, b2, p_fo2, BSZ * 512, 2048, 128, 2048);
    k_conv_layer<<<dim3(512, BSZ), 256>>>(vertices, NV, 512, p_nb1, p_fo2, p_d2, 256, p_cv2);
    k_bn_stats_at<<<dim3(256 / 32, 8), dim3(32, 32)>>>(p_cv2, BSZ * 512, 256, s2, q2);
    k_bn_apply<<<cdiv(BSZ * 512 * 256, 256), 256>>>(p_cv2, s2, q2, g_bn2, be_bn2,
                                                    p_f23, BSZ * 512 * 256, 256, 512, 0,
                                                    1.f / (BSZ * 512), p_fm2);

    // layer3
    k_gemm_bf16x3<false, false, true><<<dim3(2048 / 128, BSZ * 512 / 128), 256>>>(
        p_fm2, w3, b3, p_fo3, BSZ * 512, 2048, 256, 2048);
    k_conv_layer<<<dim3(512, BSZ), 256>>>(vertices, NV, 512, p_nb1, p_fo3, p_d3, 256, p_cv3);
    k_bn_stats_at<<<dim3(256 / 32, 8), dim3(32, 32)>>>(p_cv3, BSZ * 512, 256, s3, q3);
    k_bn_apply<<<cdiv(BSZ * 512 * 256, 256), 256>>>(p_cv3, s3, q3, g_bn3, be_bn3,
                                                    p_f23, BSZ * 512 * 256, 256, 512, 256,
                                                    1.f / (BSZ * 512), p_fm3);

    // fork: pB GEMM depends only on f23
    cudaEventRecord(ev_bn3, 0);
    cudaStreamWaitEvent(s_b, ev_bn3, 0);
    k_gemm_bf16x3<true, false, false><<<dim3(512 / 128, BSZ * 512 / 128), 256, 0, s_b>>>(
        p_f23, wc1 + 256, nullptr, p_pB, BSZ * 512, 512, 512, 1808);
    cudaEventRecord(ev_pb, s_b);

    // pool2
    k_pool<<<dim3(128, BSZ), 256>>>(p_fm3, 512, p_nbp2, 256, p_fp2);

    // layer4
    k_gemm_bf16x3<false, false, true><<<dim3(4096 / 128, BSZ * 128 / 128), 256>>>(
        p_fp2, w4, b4, p_fo4, BSZ * 128, 4096, 256, 4096);
    k_conv_layer<<<dim3(128, BSZ), 512>>>(vertices, NV, 128, p_nb2, p_fo4, p_d4, 512, p_fm4);

    // fork: assemble/feat on s_a
    cudaEventRecord(ev_l4, 0);
    cudaStreamWaitEvent(s_a, ev_l4, 0);
    float* feat_out = out + (size_t)BSZ * NV * 6 + (size_t)BSZ * NV * 24;
    k_assemble<<<dim3(NV, BSZ), 256, 0, s_a>>>(p_fm0, p_fm1, p_fm2, p_fm3, p_fm4, onehot,
                                               p_n1, p_n2, feat_out);
    cudaEventRecord(ev_asm, s_a);

    // global max + pde + pC on main
    k_fglobal<<<BSZ, 512>>>(p_fm4, p_fg);
    k_pde<<<dim3(64, BSZ), 256>>>(p_fg, onehot, wc1, bc1, p_pDE);
    k_gemm_bf16x3<true, false, false><<<dim3(512 / 128, BSZ * 128 / 128), 256>>>(
        p_fm4, wc1 + 768, nullptr, p_pC, BSZ * 128, 512, 512, 1808);

    // join pA, pB, n1/n2 then combine
    cudaStreamWaitEvent(0, ev_pa, 0);
    cudaStreamWaitEvent(0, ev_pb, 0);
    cudaStreamWaitEvent(0, ev_ja, 0);
    k_combine<<<BSZ * NV, 128>>>(p_pA, p_pB, p_pC, p_pDE, p_n1, p_n2, p_h1);

    // rest of MLP; head writes seg/vecs directly into d_out
    k_gemm_bf16x3<true, true, true><<<dim3(512 / 128, BSZ * NV / 128), 256>>>(
        p_h1, wc2, bc2, p_h2, BSZ * NV, 512, 512, 512);
    k_gemm_head<<<dim3(1, BSZ * NV / BM), 256>>>(p_h2, wc3, bc3, out, BSZ * NV, 512);

    // join assemble before returning
    cudaStreamWaitEvent(0, ev_asm, 0);
}